// round 8
// baseline (speedup 1.0000x reference)
#include <cuda_runtime.h>
#include <cstdint>

#define D_MODEL 512
#define NH 8
#define DH 64

// Scratch (allocation-free rule: __device__ globals).
__device__ float g_q[4096 * 512];
__device__ float g_k[4096 * 512];
__device__ float g_v[4096 * 512];
__device__ float g_att[4096 * 512];
// Split-KV partials: up to 4 chunks per q-row (chunk = 8 kb-iters).
__device__ float g_op[4 * 4096 * 512];
__device__ float g_m[4 * 8 * 4096];
__device__ float g_l[4 * 8 * 4096];

// Work-item table: 40 items per bh -> (qb, chunk). nchunks(qb) = qb/4 + 1.
__constant__ unsigned char c_qb[40] = {
    0, 1, 2, 3, 4, 4, 5, 5, 6, 6, 7, 7, 8, 8, 8, 9, 9, 9, 10, 10,
    10, 11, 11, 11, 12, 12, 12, 12, 13, 13, 13, 13, 14, 14, 14, 14, 15, 15, 15, 15};
__constant__ unsigned char c_ch[40] = {
    0, 0, 0, 0, 0, 1, 0, 1, 0, 1, 0, 1, 0, 1, 2, 0, 1, 2, 0, 1,
    2, 0, 1, 2, 0, 1, 2, 3, 0, 1, 2, 3, 0, 1, 2, 3, 0, 1, 2, 3};

__device__ __forceinline__ float f2tf32(float x) {
    uint32_t y;
    asm("cvt.rna.tf32.f32 %0, %1;" : "=r"(y) : "f"(x));
    return __uint_as_float(y);
}

__device__ __forceinline__ void mma_tf32(float* c, uint32_t a0, uint32_t a1,
                                         uint32_t a2, uint32_t a3, uint32_t b0,
                                         uint32_t b1) {
    asm volatile(
        "mma.sync.aligned.m16n8k8.row.col.f32.tf32.tf32.f32 "
        "{%0,%1,%2,%3}, {%4,%5,%6,%7}, {%8,%9}, {%0,%1,%2,%3};"
        : "+f"(c[0]), "+f"(c[1]), "+f"(c[2]), "+f"(c[3])
        : "r"(a0), "r"(a1), "r"(a2), "r"(a3), "r"(b0), "r"(b1));
}

__device__ __forceinline__ void mma_tf32f(float* c, float a0, float a1, float a2,
                                          float a3, float b0, float b1) {
    mma_tf32(c, __float_as_uint(a0), __float_as_uint(a1), __float_as_uint(a2),
             __float_as_uint(a3), __float_as_uint(b0), __float_as_uint(b1));
}

__device__ __forceinline__ void cp_async16(void* smem_dst, const void* gmem_src) {
    uint32_t s = (uint32_t)__cvta_generic_to_shared(smem_dst);
    asm volatile("cp.async.cg.shared.global [%0], [%1], 16;\n" ::"r"(s),
                 "l"(gmem_src));
}
#define CP_COMMIT() asm volatile("cp.async.commit_group;\n" ::: "memory")
#define CP_WAIT0() asm volatile("cp.async.wait_group 0;\n" ::: "memory")

// ---------------------------------------------------------------------------
// C[M,512] = A[M,512] @ W[512,512]^T  via tf32 mma, cp.async 2-stage pipeline.
// BM=128, BN=128, BK=32. 256 threads = 8 warps (2m x 4n), warp tile 64x32.
// blockIdx.z selects one of 3 (A, W, C) triples. Per-z output mode (packed 2
// bits each in modes): 0 = plain; 1 = perm4 (c -> (c%4)*16 + c/4 within each
// 64-col head block); 2 = perm8 (c -> (c%8)*8 + c/8). Permuted outputs are
// staged through smem so the global stores stay fully coalesced (STG.128).
// ---------------------------------------------------------------------------
#define GSTR 36
#define SMEM_GEMM (2 * 2 * 128 * GSTR * 4)  // 73728 B; staging needs 67584 B

template <int ROUND_OUT>
__global__ void __launch_bounds__(256, 2)
    gemm_xwT(const float* __restrict__ A0, const float* __restrict__ W0,
             float* __restrict__ C0, const float* __restrict__ A1,
             const float* __restrict__ W1, float* __restrict__ C1,
             const float* __restrict__ A2, const float* __restrict__ W2,
             float* __restrict__ C2, int modes) {
    extern __shared__ float smg[];
    float* As = smg;                    // [2][128][GSTR]
    float* Ws = smg + 2 * 128 * GSTR;   // [2][128][GSTR]

    const int z = blockIdx.z;
    const float* A = (z == 0) ? A0 : (z == 1) ? A1 : A2;
    const float* W = (z == 0) ? W0 : (z == 1) ? W1 : W2;
    float* C = (z == 0) ? C0 : (z == 1) ? C1 : C2;
    const int mode = (modes >> (2 * z)) & 3;

    const int tid = threadIdx.x;
    const int lane = tid & 31, wid = tid >> 5;
    const int g = lane >> 2, tg = lane & 3;
    const int warp_m = wid >> 2, warp_n = wid & 3;
    const int row0 = blockIdx.x * 128, col0 = blockIdx.y * 128;

    float acc[4][4][4];
#pragma unroll
    for (int mi = 0; mi < 4; mi++)
#pragma unroll
        for (int ni = 0; ni < 4; ni++)
#pragma unroll
            for (int c = 0; c < 4; c++) acc[mi][ni][c] = 0.f;

    auto load_stage = [&](int k0, int st) {
        float* Ad = As + st * 128 * GSTR;
        float* Wd = Ws + st * 128 * GSTR;
#pragma unroll
        for (int i = 0; i < 4; i++) {
            const int f4 = tid + i * 256;
            const int r = f4 >> 3, c = (f4 & 7) * 4;
            cp_async16(Ad + r * GSTR + c, A + (size_t)(row0 + r) * D_MODEL + k0 + c);
            cp_async16(Wd + r * GSTR + c, W + (size_t)(col0 + r) * D_MODEL + k0 + c);
        }
        CP_COMMIT();
    };

    load_stage(0, 0);

    for (int it = 0; it < 16; it++) {
        CP_WAIT0();
        __syncthreads();
        if (it + 1 < 16) load_stage((it + 1) * 32, (it + 1) & 1);

        const float* Ab = As + (it & 1) * 128 * GSTR;
        const float* Wb = Ws + (it & 1) * 128 * GSTR;
#pragma unroll
        for (int ks = 0; ks < 4; ks++) {
            const int kk = ks * 8;
            uint32_t a[4][4];
#pragma unroll
            for (int mi = 0; mi < 4; mi++) {
                const int rm = warp_m * 64 + mi * 16;
                a[mi][0] = __float_as_uint(f2tf32(Ab[(rm + g) * GSTR + kk + tg]));
                a[mi][1] = __float_as_uint(f2tf32(Ab[(rm + 8 + g) * GSTR + kk + tg]));
                a[mi][2] = __float_as_uint(f2tf32(Ab[(rm + g) * GSTR + kk + tg + 4]));
                a[mi][3] = __float_as_uint(f2tf32(Ab[(rm + 8 + g) * GSTR + kk + tg + 4]));
            }
#pragma unroll
            for (int ni = 0; ni < 4; ni++) {
                const int nb = warp_n * 32 + ni * 8;
                uint32_t b0 = __float_as_uint(f2tf32(Wb[(nb + g) * GSTR + kk + tg]));
                uint32_t b1 = __float_as_uint(f2tf32(Wb[(nb + g) * GSTR + kk + tg + 4]));
#pragma unroll
                for (int mi = 0; mi < 4; mi++)
                    mma_tf32(acc[mi][ni], a[mi][0], a[mi][1], a[mi][2], a[mi][3],
                             b0, b1);
            }
        }
    }

    if (mode == 0) {
#pragma unroll
        for (int mi = 0; mi < 4; mi++) {
#pragma unroll
            for (int ni = 0; ni < 4; ni++) {
                const int r = row0 + warp_m * 64 + mi * 16 + g;
                const int c = col0 + warp_n * 32 + ni * 8 + 2 * tg;
                float v0 = acc[mi][ni][0], v1 = acc[mi][ni][1];
                float v2 = acc[mi][ni][2], v3 = acc[mi][ni][3];
                if (ROUND_OUT) {
                    v0 = f2tf32(v0); v1 = f2tf32(v1);
                    v2 = f2tf32(v2); v3 = f2tf32(v3);
                }
                *(float2*)(C + (size_t)r * D_MODEL + c) = make_float2(v0, v1);
                *(float2*)(C + (size_t)(r + 8) * D_MODEL + c) = make_float2(v2, v3);
            }
        }
    } else {
        // Stage into smem (plain layout), then permuted gather + coalesced store.
        __syncthreads();  // all warps done reading As/Ws
        float* Cs = smg;  // [128][132]
#pragma unroll
        for (int mi = 0; mi < 4; mi++) {
#pragma unroll
            for (int ni = 0; ni < 4; ni++) {
                const int r = warp_m * 64 + mi * 16 + g;
                const int c = warp_n * 32 + ni * 8 + 2 * tg;
                float v0 = acc[mi][ni][0], v1 = acc[mi][ni][1];
                float v2 = acc[mi][ni][2], v3 = acc[mi][ni][3];
                if (ROUND_OUT) {
                    v0 = f2tf32(v0); v1 = f2tf32(v1);
                    v2 = f2tf32(v2); v3 = f2tf32(v3);
                }
                Cs[r * 132 + c] = v0;
                Cs[r * 132 + c + 1] = v1;
                Cs[(r + 8) * 132 + c] = v2;
                Cs[(r + 8) * 132 + c + 1] = v3;
            }
        }
        __syncthreads();
        const bool p8 = (mode == 2);
#pragma unroll
        for (int i = 0; i < 16; i++) {
            const int idx = tid + i * 256;       // float4 units of [128][32]
            const int r = idx >> 5;
            const int p0 = (idx & 31) * 4;       // 0..124
            const int blk = p0 & 64;             // head block base (0 or 64)
            const int pw = p0 & 63;
            float o[4];
#pragma unroll
            for (int j = 0; j < 4; j++) {
                const int p = pw + j;
                const int cw = p8 ? ((p & 7) * 8 + (p >> 3))
                                  : ((p & 15) * 4 + (p >> 4));
                o[j] = Cs[r * 132 + blk + cw];
            }
            *(float4*)(C + (size_t)(row0 + r) * D_MODEL + col0 + p0) =
                make_float4(o[0], o[1], o[2], o[3]);
        }
    }
}

// ---------------------------------------------------------------------------
// Split-KV flash attention, tf32 mma. Br=128, Bc=64, 256 threads (8 warps x
// 16 rows). Each block: one (bh, q-tile, 8-iteration KV chunk) -> writes
// UNNORMALIZED O partial + per-row (m, l).
// Q,K arrive perm4-interleaved, V perm8-interleaved (written by projection
// epilogues) so ALL fragment loads are LDS128. Partials written plain.
// ---------------------------------------------------------------------------
#define QSTR 68
#define VSTR 68
#define SMEM_ATTN ((128 * QSTR + 2 * 64 * QSTR + 2 * 64 * VSTR) * 4)

__global__ void __launch_bounds__(256, 2)
    attn_kernel(const float* __restrict__ Qg, const float* __restrict__ Kg,
                const float* __restrict__ Vg, float* __restrict__ Op,
                float* __restrict__ Mp, float* __restrict__ Lp, int SEQ) {
    extern __shared__ float sm[];
    float* Qs = sm;                         // [128][QSTR] perm4
    float* Ks = sm + 128 * QSTR;            // [2][64][QSTR] perm4
    float* Vs = Ks + 2 * 64 * QSTR;         // [2][64][VSTR] perm8

    const float inv_scale = 0.044194173824159216f;  // 1/sqrt(512)
    const int tid = threadIdx.x;
    const int lane = tid & 31, wid = tid >> 5;
    const int g = lane >> 2, tg = lane & 3;
    const int r0 = wid * 16;
    const int bh = blockIdx.x / 40;
    const int item = blockIdx.x % 40;
    const int qb = c_qb[item];
    const int ch = c_ch[item];
    const int b = bh >> 3, h = bh & 7;
    const size_t rowbase = (size_t)b * SEQ;
    const int colh = h * DH;
    const int kbmax = 2 * qb + 1;
    const int kb0 = ch * 8;
    const int kbe = min(kb0 + 7, kbmax);

    auto load_kv = [&](int kb, int st) {
        const float* Kb = Kg + (rowbase + kb * 64) * D_MODEL + colh;
        const float* Vb = Vg + (rowbase + kb * 64) * D_MODEL + colh;
        float* Kd = Ks + st * 64 * QSTR;
        float* Vd = Vs + st * 64 * VSTR;
#pragma unroll
        for (int i = 0; i < 4; i++) {
            const int f4 = tid + i * 256;
            const int r = f4 >> 4, c = (f4 & 15) * 4;
            cp_async16(Kd + r * QSTR + c, Kb + (size_t)r * D_MODEL + c);
            cp_async16(Vd + r * VSTR + c, Vb + (size_t)r * D_MODEL + c);
        }
        CP_COMMIT();
    };

    load_kv(kb0, kb0 & 1);

    // Q tile [128 x 64] (pre-rounded tf32, perm4): raw copy
#pragma unroll
    for (int i = 0; i < 8; i++) {
        const int f4 = tid + i * 256;
        const int r = f4 >> 4, c = (f4 & 15) * 4;
        float4 v = *(const float4*)(Qg + (rowbase + qb * 128 + r) * D_MODEL + colh + c);
        Qs[r * QSTR + c + 0] = v.x; Qs[r * QSTR + c + 1] = v.y;
        Qs[r * QSTR + c + 2] = v.z; Qs[r * QSTR + c + 3] = v.w;
    }

    float m[2] = {-1e30f, -1e30f}, l[2] = {0.f, 0.f};
    float oacc[8][4];
#pragma unroll
    for (int ni = 0; ni < 8; ni++)
#pragma unroll
        for (int c = 0; c < 4; c++) oacc[ni][c] = 0.f;

    for (int kb = kb0; kb <= kbe; kb++) {
        CP_WAIT0();
        __syncthreads();
        if (kb + 1 <= kbe) load_kv(kb + 1, (kb + 1) & 1);

        const float* Kb = Ks + (kb & 1) * 64 * QSTR;
        const float* Vb = Vs + (kb & 1) * 64 * VSTR;

        const int joff = kb * 64 - qb * 128;
        if (joff > r0 + 15) continue;           // warp fully masked
        const bool need_mask = (joff + 63 > r0);

        float sacc[8][4];
#pragma unroll
        for (int ni = 0; ni < 8; ni++)
#pragma unroll
            for (int c = 0; c < 4; c++) sacc[ni][c] = 0.f;

        // S = Q K^T. perm4 layout: row's 16 lane-needed values (cols == tg
        // mod 4) are contiguous at [tg*16 .. tg*16+15]; element 2ksi = col
        // 8ks+tg (a0/b0), 2ksi+1 = col 8ks+tg+4 (a2/b1), ks = half*4+ksi.
#pragma unroll
        for (int half = 0; half < 2; half++) {
            const int off = tg * 16 + half * 8;
            float A0[8], A1[8];
            {
                float4 t0 = *(const float4*)&Qs[(r0 + g) * QSTR + off];
                float4 t1 = *(const float4*)&Qs[(r0 + g) * QSTR + off + 4];
                A0[0] = t0.x; A0[1] = t0.y; A0[2] = t0.z; A0[3] = t0.w;
                A0[4] = t1.x; A0[5] = t1.y; A0[6] = t1.z; A0[7] = t1.w;
                float4 u0 = *(const float4*)&Qs[(r0 + 8 + g) * QSTR + off];
                float4 u1 = *(const float4*)&Qs[(r0 + 8 + g) * QSTR + off + 4];
                A1[0] = u0.x; A1[1] = u0.y; A1[2] = u0.z; A1[3] = u0.w;
                A1[4] = u1.x; A1[5] = u1.y; A1[6] = u1.z; A1[7] = u1.w;
            }
#pragma unroll
            for (int ni = 0; ni < 8; ni++) {
                float Bv[8];
                float4 k0 = *(const float4*)&Kb[(ni * 8 + g) * QSTR + off];
                float4 k1 = *(const float4*)&Kb[(ni * 8 + g) * QSTR + off + 4];
                Bv[0] = k0.x; Bv[1] = k0.y; Bv[2] = k0.z; Bv[3] = k0.w;
                Bv[4] = k1.x; Bv[5] = k1.y; Bv[6] = k1.z; Bv[7] = k1.w;
#pragma unroll
                for (int ksi = 0; ksi < 4; ksi++)
                    mma_tf32f(sacc[ni], A0[2 * ksi], A1[2 * ksi], A0[2 * ksi + 1],
                              A1[2 * ksi + 1], Bv[2 * ksi], Bv[2 * ksi + 1]);
            }
        }

        // scale + causal mask ((x-1e10)/scale underflows expf to 0 == -1e30)
#pragma unroll
        for (int ni = 0; ni < 8; ni++)
#pragma unroll
            for (int c = 0; c < 4; c++) {
                float sv = sacc[ni][c] * inv_scale;
                if (need_mask) {
                    const int j = joff + ni * 8 + 2 * tg + (c & 1);
                    const int r = r0 + g + (c >> 1) * 8;
                    if (j > r) sv = -1e30f;
                }
                sacc[ni][c] = sv;
            }

        // online softmax per row-half
#pragma unroll
        for (int i = 0; i < 2; i++) {
            float rmax = -1e30f;
#pragma unroll
            for (int ni = 0; ni < 8; ni++)
                rmax = fmaxf(rmax, fmaxf(sacc[ni][i * 2], sacc[ni][i * 2 + 1]));
            rmax = fmaxf(rmax, __shfl_xor_sync(0xffffffffu, rmax, 1));
            rmax = fmaxf(rmax, __shfl_xor_sync(0xffffffffu, rmax, 2));
            const float mnew = fmaxf(m[i], rmax);
            const float corr = __expf(m[i] - mnew);
            float rsum = 0.f;
#pragma unroll
            for (int ni = 0; ni < 8; ni++) {
                float p0 = __expf(sacc[ni][i * 2] - mnew);
                float p1 = __expf(sacc[ni][i * 2 + 1] - mnew);
                sacc[ni][i * 2] = p0;
                sacc[ni][i * 2 + 1] = p1;
                rsum += p0 + p1;
            }
            rsum += __shfl_xor_sync(0xffffffffu, rsum, 1);
            rsum += __shfl_xor_sync(0xffffffffu, rsum, 2);
            l[i] = l[i] * corr + rsum;
            m[i] = mnew;
#pragma unroll
            for (int ni = 0; ni < 8; ni++) {
                oacc[ni][i * 2] *= corr;
                oacc[ni][i * 2 + 1] *= corr;
            }
        }

        // O += P V. A from intra-quad shuffles; B from perm8 V: col ni*8+g
        // lives at p = g*8 + ni -> lane's 8 values contiguous at [g*8..g*8+7].
        const int src0 = (lane & ~3) | (tg >> 1);
        const bool odd = tg & 1;
#pragma unroll
        for (int ks = 0; ks < 8; ks++) {
            float p00 = __shfl_sync(0xffffffffu, sacc[ks][0], src0);
            float p01 = __shfl_sync(0xffffffffu, sacc[ks][1], src0);
            float p10 = __shfl_sync(0xffffffffu, sacc[ks][2], src0);
            float p11 = __shfl_sync(0xffffffffu, sacc[ks][3], src0);
            float q00 = __shfl_sync(0xffffffffu, sacc[ks][0], src0 + 2);
            float q01 = __shfl_sync(0xffffffffu, sacc[ks][1], src0 + 2);
            float q10 = __shfl_sync(0xffffffffu, sacc[ks][2], src0 + 2);
            float q11 = __shfl_sync(0xffffffffu, sacc[ks][3], src0 + 2);
            const float a0 = f2tf32(odd ? p01 : p00);
            const float a1 = f2tf32(odd ? p11 : p10);
            const float a2 = f2tf32(odd ? q01 : q00);
            const float a3 = f2tf32(odd ? q11 : q10);
            const int j0 = ks * 8;
            float B0[8], B1[8];
            {
                float4 v0l = *(const float4*)&Vb[(j0 + tg) * VSTR + g * 8];
                float4 v0h = *(const float4*)&Vb[(j0 + tg) * VSTR + g * 8 + 4];
                B0[0] = v0l.x; B0[1] = v0l.y; B0[2] = v0l.z; B0[3] = v0l.w;
                B0[4] = v0h.x; B0[5] = v0h.y; B0[6] = v0h.z; B0[7] = v0h.w;
                float4 v1l = *(const float4*)&Vb[(j0 + tg + 4) * VSTR + g * 8];
                float4 v1h = *(const float4*)&Vb[(j0 + tg + 4) * VSTR + g * 8 + 4];
                B1[0] = v1l.x; B1[1] = v1l.y; B1[2] = v1l.z; B1[3] = v1l.w;
                B1[4] = v1h.x; B1[5] = v1h.y; B1[6] = v1h.z; B1[7] = v1h.w;
            }
#pragma unroll
            for (int ni = 0; ni < 8; ni++)
                mma_tf32f(oacc[ni], a0, a1, a2, a3, B0[ni], B1[ni]);
        }
    }

    // Write UNNORMALIZED partials + (m, l)  (plain layout)
    float* op = Op + (size_t)ch * 4096 * 512;
    const size_t rA = rowbase + qb * 128 + r0 + g;
#pragma unroll
    for (int ni = 0; ni < 8; ni++) {
        const int c = colh + ni * 8 + 2 * tg;
        *(float2*)(op + rA * D_MODEL + c) = make_float2(oacc[ni][0], oacc[ni][1]);
        *(float2*)(op + (rA + 8) * D_MODEL + c) = make_float2(oacc[ni][2], oacc[ni][3]);
    }
    if (tg == 0) {
        const size_t mlb = (size_t)(ch * 8 + h) * 4096;
        Mp[mlb + rA] = m[0];
        Lp[mlb + rA] = l[0];
        Mp[mlb + rA + 8] = m[1];
        Lp[mlb + rA + 8] = l[1];
    }
}

// ---------------------------------------------------------------------------
// Combine split-KV partials: exact softmax merge, then normalize.
// ---------------------------------------------------------------------------
__global__ void __launch_bounds__(256) combine_kernel(
    const float* __restrict__ Op, const float* __restrict__ Mp,
    const float* __restrict__ Lp, float* __restrict__ Og) {
    const int tid = threadIdx.x;
    const int u = blockIdx.x * 8 + (tid >> 5);  // (row, head) unit
    const int row = u >> 3, h = u & 7;
    const int j = (tid & 31) * 2;
    const int qb = (row >> 7) & 15;
    const int nch = (qb >> 2) + 1;

    float mv[4], lv[4];
    float mg = -1e30f;
#pragma unroll
    for (int c = 0; c < 4; c++)
        if (c < nch) {
            mv[c] = Mp[(size_t)(c * 8 + h) * 4096 + row];
            lv[c] = Lp[(size_t)(c * 8 + h) * 4096 + row];
            mg = fmaxf(mg, mv[c]);
        }
    float lg = 0.f;
    float2 o = make_float2(0.f, 0.f);
#pragma unroll
    for (int c = 0; c < 4; c++)
        if (c < nch) {
            const float sc = __expf(mv[c] - mg);
            lg += sc * lv[c];
            float2 p = *(const float2*)(Op + (size_t)c * 4096 * 512 +
                                        (size_t)row * 512 + h * 64 + j);
            o.x += sc * p.x;
            o.y += sc * p.y;
        }
    const float inv = 1.f / lg;
    *(float2*)(Og + (size_t)row * 512 + h * 64 + j) =
        make_float2(o.x * inv, o.y * inv);
}

// ---------------------------------------------------------------------------
extern "C" void kernel_launch(void* const* d_in, const int* in_sizes, int n_in,
                              void* d_out, int out_size) {
    const float* q  = (const float*)d_in[0];
    const float* k  = (const float*)d_in[1];
    const float* v  = (const float*)d_in[2];
    const float* wq = (const float*)d_in[3];
    const float* wk = (const float*)d_in[4];
    const float* wv = (const float*)d_in[5];
    const float* wo = (const float*)d_in[6];
    float* out = (float*)d_out;

    const int M = in_sizes[0] / D_MODEL;  // B*S = 4096
    const int B = 2;
    const int SEQ = M / B;                // 2048

    float *gq, *gk, *gv, *ga, *gop, *gm, *gl;
    cudaGetSymbolAddress((void**)&gq, g_q);
    cudaGetSymbolAddress((void**)&gk, g_k);
    cudaGetSymbolAddress((void**)&gv, g_v);
    cudaGetSymbolAddress((void**)&ga, g_att);
    cudaGetSymbolAddress((void**)&gop, g_op);
    cudaGetSymbolAddress((void**)&gm, g_m);
    cudaGetSymbolAddress((void**)&gl, g_l);

    cudaFuncSetAttribute(gemm_xwT<1>,
                         cudaFuncAttributeMaxDynamicSharedMemorySize, SMEM_GEMM);
    cudaFuncSetAttribute(gemm_xwT<0>,
                         cudaFuncAttributeMaxDynamicSharedMemorySize, SMEM_GEMM);
    cudaFuncSetAttribute(attn_kernel, cudaFuncAttributeMaxDynamicSharedMemorySize,
                         SMEM_ATTN);

    // Fused projection: q/k/v in one launch. Modes: Q=perm4(1), K=perm4(1),
    // V=perm8(2) -> packed 1 | 1<<2 | 2<<4 = 37.
    dim3 gg3(M / 128, D_MODEL / 128, 3);
    gemm_xwT<1><<<gg3, 256, SMEM_GEMM>>>(q, wq, gq, k, wk, gk, v, wv, gv, 37);

    // Split-KV attention: 16 bh x 40 (qb, chunk) items, 8 kb-iters each.
    attn_kernel<<<16 * 40, 256, SMEM_ATTN>>>(gq, gk, gv, gop, gm, gl, SEQ);

    // Combine partials -> g_att
    combine_kernel<<<4096 * 8 / 8, 256>>>(gop, gm, gl, ga);

    // Output projection (plain in/out)
    dim3 gg1(M / 128, D_MODEL / 128, 1);
    gemm_xwT<0><<<gg1, 256, SMEM_GEMM>>>(ga, wo, out, ga, wo, out, ga, wo, out, 0);
}

// round 9
// speedup vs baseline: 1.2179x; 1.2179x over previous
#include <cuda_runtime.h>
#include <cstdint>

#define D_MODEL 512
#define NH 8
#define DH 64

// Scratch (allocation-free rule: __device__ globals).
__device__ float g_q[4096 * 512];
__device__ float g_k[4096 * 512];
__device__ float g_v[4096 * 512];
__device__ float g_att[4096 * 512];
__device__ float g_wr[4 * 512 * 512];  // tf32-rounded weights (wq,wk,wv,wo)
// Split-KV partials: up to 4 chunks per q-row (chunk = 8 kb-iters).
__device__ float g_op[4 * 4096 * 512];
__device__ float g_m[4 * 8 * 4096];
__device__ float g_l[4 * 8 * 4096];

// Work-item table: 40 items per bh -> (qb, chunk). nchunks(qb) = qb/4 + 1.
__constant__ unsigned char c_qb[40] = {
    0, 1, 2, 3, 4, 4, 5, 5, 6, 6, 7, 7, 8, 8, 8, 9, 9, 9, 10, 10,
    10, 11, 11, 11, 12, 12, 12, 12, 13, 13, 13, 13, 14, 14, 14, 14, 15, 15, 15, 15};
__constant__ unsigned char c_ch[40] = {
    0, 0, 0, 0, 0, 1, 0, 1, 0, 1, 0, 1, 0, 1, 2, 0, 1, 2, 0, 1,
    2, 0, 1, 2, 0, 1, 2, 3, 0, 1, 2, 3, 0, 1, 2, 3, 0, 1, 2, 3};

__device__ __forceinline__ float f2tf32(float x) {
    uint32_t y;
    asm("cvt.rna.tf32.f32 %0, %1;" : "=r"(y) : "f"(x));
    return __uint_as_float(y);
}

__device__ __forceinline__ void mma_tf32(float* c, uint32_t a0, uint32_t a1,
                                         uint32_t a2, uint32_t a3, uint32_t b0,
                                         uint32_t b1) {
    asm volatile(
        "mma.sync.aligned.m16n8k8.row.col.f32.tf32.tf32.f32 "
        "{%0,%1,%2,%3}, {%4,%5,%6,%7}, {%8,%9}, {%0,%1,%2,%3};"
        : "+f"(c[0]), "+f"(c[1]), "+f"(c[2]), "+f"(c[3])
        : "r"(a0), "r"(a1), "r"(a2), "r"(a3), "r"(b0), "r"(b1));
}

__device__ __forceinline__ void cp_async16(void* smem_dst, const void* gmem_src) {
    uint32_t s = (uint32_t)__cvta_generic_to_shared(smem_dst);
    asm volatile("cp.async.cg.shared.global [%0], [%1], 16;\n" ::"r"(s),
                 "l"(gmem_src));
}
#define CP_COMMIT() asm volatile("cp.async.commit_group;\n" ::: "memory")
#define CP_WAIT0() asm volatile("cp.async.wait_group 0;\n" ::: "memory")

// ---------------------------------------------------------------------------
// Round the 4 weight matrices (512x512 each) to tf32 once.
// ---------------------------------------------------------------------------
__global__ void __launch_bounds__(256) round_w(const float4* __restrict__ w0,
                                               const float4* __restrict__ w1,
                                               const float4* __restrict__ w2,
                                               const float4* __restrict__ w3,
                                               float4* __restrict__ out) {
    const int i = blockIdx.x * 256 + threadIdx.x;  // float4 index, 0..262143
    const int which = i >> 16;                     // 65536 float4 per matrix
    const int j = i & 65535;
    const float4 v = (which == 0) ? w0[j] : (which == 1) ? w1[j]
                     : (which == 2) ? w2[j] : w3[j];
    out[i] = make_float4(f2tf32(v.x), f2tf32(v.y), f2tf32(v.z), f2tf32(v.w));
}

// ---------------------------------------------------------------------------
// C[M,512] = A[M,512] @ W[512,512]^T  via tf32 mma, cp.async 2-stage pipeline.
// BM=128, BN=128, BK=32. 256 threads = 8 warps (2m x 4n), warp tile 64x32.
// blockIdx.z selects one of 3 (A, W, C) triples. W must be pre-rounded tf32
// (no cvt on W fragments). CVT_A: round A fragments at load (for raw inputs);
// 0 when A is already tf32 (wo-GEMM reading combine output).
// ---------------------------------------------------------------------------
#define GSTR 36
#define SMEM_GEMM (2 * 2 * 128 * GSTR * 4)

template <int ROUND_OUT, int CVT_A>
__global__ void __launch_bounds__(256, 2)
    gemm_xwT(const float* __restrict__ A0, const float* __restrict__ W0,
             float* __restrict__ C0, const float* __restrict__ A1,
             const float* __restrict__ W1, float* __restrict__ C1,
             const float* __restrict__ A2, const float* __restrict__ W2,
             float* __restrict__ C2) {
    extern __shared__ float smg[];
    float* As = smg;                    // [2][128][GSTR]
    float* Ws = smg + 2 * 128 * GSTR;   // [2][128][GSTR]

    const int z = blockIdx.z;
    const float* A = (z == 0) ? A0 : (z == 1) ? A1 : A2;
    const float* W = (z == 0) ? W0 : (z == 1) ? W1 : W2;
    float* C = (z == 0) ? C0 : (z == 1) ? C1 : C2;

    const int tid = threadIdx.x;
    const int lane = tid & 31, wid = tid >> 5;
    const int g = lane >> 2, tg = lane & 3;
    const int warp_m = wid >> 2, warp_n = wid & 3;
    const int row0 = blockIdx.x * 128, col0 = blockIdx.y * 128;

    float acc[4][4][4];
#pragma unroll
    for (int mi = 0; mi < 4; mi++)
#pragma unroll
        for (int ni = 0; ni < 4; ni++)
#pragma unroll
            for (int c = 0; c < 4; c++) acc[mi][ni][c] = 0.f;

    auto load_stage = [&](int k0, int st) {
        float* Ad = As + st * 128 * GSTR;
        float* Wd = Ws + st * 128 * GSTR;
#pragma unroll
        for (int i = 0; i < 4; i++) {
            const int f4 = tid + i * 256;
            const int r = f4 >> 3, c = (f4 & 7) * 4;
            cp_async16(Ad + r * GSTR + c, A + (size_t)(row0 + r) * D_MODEL + k0 + c);
            cp_async16(Wd + r * GSTR + c, W + (size_t)(col0 + r) * D_MODEL + k0 + c);
        }
        CP_COMMIT();
    };

    load_stage(0, 0);

    for (int it = 0; it < 16; it++) {
        CP_WAIT0();
        __syncthreads();
        if (it + 1 < 16) load_stage((it + 1) * 32, (it + 1) & 1);

        const float* Ab = As + (it & 1) * 128 * GSTR;
        const float* Wb = Ws + (it & 1) * 128 * GSTR;
#pragma unroll
        for (int ks = 0; ks < 4; ks++) {
            const int kk = ks * 8;
            uint32_t a[4][4];
#pragma unroll
            for (int mi = 0; mi < 4; mi++) {
                const int rm = warp_m * 64 + mi * 16;
                float e0 = Ab[(rm + g) * GSTR + kk + tg];
                float e1 = Ab[(rm + 8 + g) * GSTR + kk + tg];
                float e2 = Ab[(rm + g) * GSTR + kk + tg + 4];
                float e3 = Ab[(rm + 8 + g) * GSTR + kk + tg + 4];
                if (CVT_A) {
                    e0 = f2tf32(e0); e1 = f2tf32(e1);
                    e2 = f2tf32(e2); e3 = f2tf32(e3);
                }
                a[mi][0] = __float_as_uint(e0);
                a[mi][1] = __float_as_uint(e1);
                a[mi][2] = __float_as_uint(e2);
                a[mi][3] = __float_as_uint(e3);
            }
#pragma unroll
            for (int ni = 0; ni < 4; ni++) {
                const int nb = warp_n * 32 + ni * 8;
                uint32_t b0 = __float_as_uint(Wb[(nb + g) * GSTR + kk + tg]);
                uint32_t b1 = __float_as_uint(Wb[(nb + g) * GSTR + kk + tg + 4]);
#pragma unroll
                for (int mi = 0; mi < 4; mi++)
                    mma_tf32(acc[mi][ni], a[mi][0], a[mi][1], a[mi][2], a[mi][3],
                             b0, b1);
            }
        }
    }

#pragma unroll
    for (int mi = 0; mi < 4; mi++) {
#pragma unroll
        for (int ni = 0; ni < 4; ni++) {
            const int r = row0 + warp_m * 64 + mi * 16 + g;
            const int c = col0 + warp_n * 32 + ni * 8 + 2 * tg;
            float v0 = acc[mi][ni][0], v1 = acc[mi][ni][1];
            float v2 = acc[mi][ni][2], v3 = acc[mi][ni][3];
            if (ROUND_OUT) {
                v0 = f2tf32(v0); v1 = f2tf32(v1);
                v2 = f2tf32(v2); v3 = f2tf32(v3);
            }
            *(float2*)(C + (size_t)r * D_MODEL + c) = make_float2(v0, v1);
            *(float2*)(C + (size_t)(r + 8) * D_MODEL + c) = make_float2(v2, v3);
        }
    }
}

// ---------------------------------------------------------------------------
// Split-KV flash attention, tf32 mma. Br=128, Bc=64, 256 threads (8 warps x
// 16 rows). Each block: one (bh, q-tile, 8-iteration KV chunk) -> writes
// UNNORMALIZED O partial + per-row (m, l). Inputs pre-rounded tf32.
// ---------------------------------------------------------------------------
#define QSTR 68
#define VSTR 72
#define SMEM_ATTN ((128 * QSTR + 2 * 64 * QSTR + 2 * 64 * VSTR) * 4)

__global__ void __launch_bounds__(256, 2)
    attn_kernel(const float* __restrict__ Qg, const float* __restrict__ Kg,
                const float* __restrict__ Vg, float* __restrict__ Op,
                float* __restrict__ Mp, float* __restrict__ Lp, int SEQ) {
    extern __shared__ float sm[];
    float* Qs = sm;                         // [128][QSTR]
    float* Ks = sm + 128 * QSTR;            // [2][64][QSTR]
    float* Vs = Ks + 2 * 64 * QSTR;         // [2][64][VSTR]

    const float inv_scale = 0.044194173824159216f;  // 1/sqrt(512)
    const int tid = threadIdx.x;
    const int lane = tid & 31, wid = tid >> 5;
    const int g = lane >> 2, tg = lane & 3;
    const int r0 = wid * 16;
    const int bh = blockIdx.x / 40;
    const int item = blockIdx.x % 40;
    const int qb = c_qb[item];
    const int ch = c_ch[item];
    const int b = bh >> 3, h = bh & 7;
    const size_t rowbase = (size_t)b * SEQ;
    const int colh = h * DH;
    const int kbmax = 2 * qb + 1;
    const int kb0 = ch * 8;
    const int kbe = min(kb0 + 7, kbmax);

    auto load_kv = [&](int kb, int st) {
        const float* Kb = Kg + (rowbase + kb * 64) * D_MODEL + colh;
        const float* Vb = Vg + (rowbase + kb * 64) * D_MODEL + colh;
        float* Kd = Ks + st * 64 * QSTR;
        float* Vd = Vs + st * 64 * VSTR;
#pragma unroll
        for (int i = 0; i < 4; i++) {
            const int f4 = tid + i * 256;
            const int r = f4 >> 4, c = (f4 & 15) * 4;
            cp_async16(Kd + r * QSTR + c, Kb + (size_t)r * D_MODEL + c);
            cp_async16(Vd + r * VSTR + c, Vb + (size_t)r * D_MODEL + c);
        }
        CP_COMMIT();
    };

    load_kv(kb0, kb0 & 1);

    // Q tile [128 x 64] (pre-rounded tf32)
#pragma unroll
    for (int i = 0; i < 8; i++) {
        const int f4 = tid + i * 256;
        const int r = f4 >> 4, c = (f4 & 15) * 4;
        float4 v = *(const float4*)(Qg + (rowbase + qb * 128 + r) * D_MODEL + colh + c);
        Qs[r * QSTR + c + 0] = v.x; Qs[r * QSTR + c + 1] = v.y;
        Qs[r * QSTR + c + 2] = v.z; Qs[r * QSTR + c + 3] = v.w;
    }

    float m[2] = {-1e30f, -1e30f}, l[2] = {0.f, 0.f};
    float oacc[8][4];
#pragma unroll
    for (int ni = 0; ni < 8; ni++)
#pragma unroll
        for (int c = 0; c < 4; c++) oacc[ni][c] = 0.f;

    for (int kb = kb0; kb <= kbe; kb++) {
        CP_WAIT0();
        __syncthreads();
        if (kb + 1 <= kbe) load_kv(kb + 1, (kb + 1) & 1);

        const float* Kb = Ks + (kb & 1) * 64 * QSTR;
        const float* Vb = Vs + (kb & 1) * 64 * VSTR;

        const int joff = kb * 64 - qb * 128;
        if (joff > r0 + 15) continue;           // warp fully masked
        const bool need_mask = (joff + 63 > r0);

        float sacc[8][4];
#pragma unroll
        for (int ni = 0; ni < 8; ni++)
#pragma unroll
            for (int c = 0; c < 4; c++) sacc[ni][c] = 0.f;

#pragma unroll
        for (int ks = 0; ks < 8; ks++) {
            const int kk = ks * 8;
            uint32_t a0 = __float_as_uint(Qs[(r0 + g) * QSTR + kk + tg]);
            uint32_t a1 = __float_as_uint(Qs[(r0 + 8 + g) * QSTR + kk + tg]);
            uint32_t a2 = __float_as_uint(Qs[(r0 + g) * QSTR + kk + tg + 4]);
            uint32_t a3 = __float_as_uint(Qs[(r0 + 8 + g) * QSTR + kk + tg + 4]);
#pragma unroll
            for (int ni = 0; ni < 8; ni++) {
                uint32_t b0 = __float_as_uint(Kb[(ni * 8 + g) * QSTR + kk + tg]);
                uint32_t b1 = __float_as_uint(Kb[(ni * 8 + g) * QSTR + kk + tg + 4]);
                mma_tf32(sacc[ni], a0, a1, a2, a3, b0, b1);
            }
        }

        // scale + causal mask ((x-1e10)/scale underflows expf to 0 == -1e30)
#pragma unroll
        for (int ni = 0; ni < 8; ni++)
#pragma unroll
            for (int c = 0; c < 4; c++) {
                float sv = sacc[ni][c] * inv_scale;
                if (need_mask) {
                    const int j = joff + ni * 8 + 2 * tg + (c & 1);
                    const int r = r0 + g + (c >> 1) * 8;
                    if (j > r) sv = -1e30f;
                }
                sacc[ni][c] = sv;
            }

        // online softmax per row-half
#pragma unroll
        for (int i = 0; i < 2; i++) {
            float rmax = -1e30f;
#pragma unroll
            for (int ni = 0; ni < 8; ni++)
                rmax = fmaxf(rmax, fmaxf(sacc[ni][i * 2], sacc[ni][i * 2 + 1]));
            rmax = fmaxf(rmax, __shfl_xor_sync(0xffffffffu, rmax, 1));
            rmax = fmaxf(rmax, __shfl_xor_sync(0xffffffffu, rmax, 2));
            const float mnew = fmaxf(m[i], rmax);
            const float corr = __expf(m[i] - mnew);
            float rsum = 0.f;
#pragma unroll
            for (int ni = 0; ni < 8; ni++) {
                float p0 = __expf(sacc[ni][i * 2] - mnew);
                float p1 = __expf(sacc[ni][i * 2 + 1] - mnew);
                sacc[ni][i * 2] = p0;
                sacc[ni][i * 2 + 1] = p1;
                rsum += p0 + p1;
            }
            rsum += __shfl_xor_sync(0xffffffffu, rsum, 1);
            rsum += __shfl_xor_sync(0xffffffffu, rsum, 2);
            l[i] = l[i] * corr + rsum;
            m[i] = mnew;
#pragma unroll
            for (int ni = 0; ni < 8; ni++) {
                oacc[ni][i * 2] *= corr;
                oacc[ni][i * 2 + 1] *= corr;
            }
        }

        // O += P V : C-fragment -> A-fragment via intra-quad shuffles
        const int src0 = (lane & ~3) | (tg >> 1);
        const bool odd = tg & 1;
#pragma unroll
        for (int ks = 0; ks < 8; ks++) {
            float p00 = __shfl_sync(0xffffffffu, sacc[ks][0], src0);
            float p01 = __shfl_sync(0xffffffffu, sacc[ks][1], src0);
            float p10 = __shfl_sync(0xffffffffu, sacc[ks][2], src0);
            float p11 = __shfl_sync(0xffffffffu, sacc[ks][3], src0);
            float q00 = __shfl_sync(0xffffffffu, sacc[ks][0], src0 + 2);
            float q01 = __shfl_sync(0xffffffffu, sacc[ks][1], src0 + 2);
            float q10 = __shfl_sync(0xffffffffu, sacc[ks][2], src0 + 2);
            float q11 = __shfl_sync(0xffffffffu, sacc[ks][3], src0 + 2);
            uint32_t a0 = __float_as_uint(f2tf32(odd ? p01 : p00));
            uint32_t a1 = __float_as_uint(f2tf32(odd ? p11 : p10));
            uint32_t a2 = __float_as_uint(f2tf32(odd ? q01 : q00));
            uint32_t a3 = __float_as_uint(f2tf32(odd ? q11 : q10));
            const int j0 = ks * 8;
#pragma unroll
            for (int ni = 0; ni < 8; ni++) {
                uint32_t b0 = __float_as_uint(Vb[(j0 + tg) * VSTR + ni * 8 + g]);
                uint32_t b1 = __float_as_uint(Vb[(j0 + tg + 4) * VSTR + ni * 8 + g]);
                mma_tf32(oacc[ni], a0, a1, a2, a3, b0, b1);
            }
        }
    }

    // Write UNNORMALIZED partials + (m, l)
    float* op = Op + (size_t)ch * 4096 * 512;
    const size_t rA = rowbase + qb * 128 + r0 + g;
#pragma unroll
    for (int ni = 0; ni < 8; ni++) {
        const int c = colh + ni * 8 + 2 * tg;
        *(float2*)(op + rA * D_MODEL + c) = make_float2(oacc[ni][0], oacc[ni][1]);
        *(float2*)(op + (rA + 8) * D_MODEL + c) = make_float2(oacc[ni][2], oacc[ni][3]);
    }
    if (tg == 0) {
        const size_t mlb = (size_t)(ch * 8 + h) * 4096;
        Mp[mlb + rA] = m[0];
        Lp[mlb + rA] = l[0];
        Mp[mlb + rA + 8] = m[1];
        Lp[mlb + rA + 8] = l[1];
    }
}

// ---------------------------------------------------------------------------
// Combine split-KV partials: exact softmax merge, normalize, round to tf32
// (so the wo-GEMM needs no cvt; identical value to cvt-at-fragment-load).
// ---------------------------------------------------------------------------
__global__ void __launch_bounds__(256) combine_kernel(
    const float* __restrict__ Op, const float* __restrict__ Mp,
    const float* __restrict__ Lp, float* __restrict__ Og) {
    const int tid = threadIdx.x;
    const int u = blockIdx.x * 8 + (tid >> 5);  // (row, head) unit
    const int row = u >> 3, h = u & 7;
    const int j = (tid & 31) * 2;
    const int qb = (row >> 7) & 15;
    const int nch = (qb >> 2) + 1;

    float mv[4], lv[4];
    float mg = -1e30f;
#pragma unroll
    for (int c = 0; c < 4; c++)
        if (c < nch) {
            mv[c] = Mp[(size_t)(c * 8 + h) * 4096 + row];
            lv[c] = Lp[(size_t)(c * 8 + h) * 4096 + row];
            mg = fmaxf(mg, mv[c]);
        }
    float lg = 0.f;
    float2 o = make_float2(0.f, 0.f);
#pragma unroll
    for (int c = 0; c < 4; c++)
        if (c < nch) {
            const float sc = __expf(mv[c] - mg);
            lg += sc * lv[c];
            float2 p = *(const float2*)(Op + (size_t)c * 4096 * 512 +
                                        (size_t)row * 512 + h * 64 + j);
            o.x += sc * p.x;
            o.y += sc * p.y;
        }
    const float inv = 1.f / lg;
    *(float2*)(Og + (size_t)row * 512 + h * 64 + j) =
        make_float2(f2tf32(o.x * inv), f2tf32(o.y * inv));
}

// ---------------------------------------------------------------------------
extern "C" void kernel_launch(void* const* d_in, const int* in_sizes, int n_in,
                              void* d_out, int out_size) {
    const float* q  = (const float*)d_in[0];
    const float* k  = (const float*)d_in[1];
    const float* v  = (const float*)d_in[2];
    const float* wq = (const float*)d_in[3];
    const float* wk = (const float*)d_in[4];
    const float* wv = (const float*)d_in[5];
    const float* wo = (const float*)d_in[6];
    float* out = (float*)d_out;

    const int M = in_sizes[0] / D_MODEL;  // B*S = 4096
    const int B = 2;
    const int SEQ = M / B;                // 2048

    float *gq, *gk, *gv, *ga, *gwr, *gop, *gm, *gl;
    cudaGetSymbolAddress((void**)&gq, g_q);
    cudaGetSymbolAddress((void**)&gk, g_k);
    cudaGetSymbolAddress((void**)&gv, g_v);
    cudaGetSymbolAddress((void**)&ga, g_att);
    cudaGetSymbolAddress((void**)&gwr, g_wr);
    cudaGetSymbolAddress((void**)&gop, g_op);
    cudaGetSymbolAddress((void**)&gm, g_m);
    cudaGetSymbolAddress((void**)&gl, g_l);

    cudaFuncSetAttribute(gemm_xwT<1, 1>,
                         cudaFuncAttributeMaxDynamicSharedMemorySize, SMEM_GEMM);
    cudaFuncSetAttribute(gemm_xwT<0, 0>,
                         cudaFuncAttributeMaxDynamicSharedMemorySize, SMEM_GEMM);
    cudaFuncSetAttribute(attn_kernel, cudaFuncAttributeMaxDynamicSharedMemorySize,
                         SMEM_ATTN);

    // Round all 4 weight matrices to tf32 once.
    round_w<<<1024, 256>>>((const float4*)wq, (const float4*)wk,
                           (const float4*)wv, (const float4*)wo, (float4*)gwr);
    const float* rwq = gwr;
    const float* rwk = gwr + 512 * 512;
    const float* rwv = gwr + 2 * 512 * 512;
    const float* rwo = gwr + 3 * 512 * 512;

    // Fused projection: q/k/v GEMMs in one launch (blockIdx.z selects).
    dim3 gg3(M / 128, D_MODEL / 128, 3);
    gemm_xwT<1, 1><<<gg3, 256, SMEM_GEMM>>>(q, rwq, gq, k, rwk, gk, v, rwv, gv);

    // Split-KV attention: 16 bh x 40 (qb, chunk) items, 8 kb-iters each.
    attn_kernel<<<16 * 40, 256, SMEM_ATTN>>>(gq, gk, gv, gop, gm, gl, SEQ);

    // Combine partials -> g_att (tf32-rounded)
    combine_kernel<<<4096 * 8 / 8, 256>>>(gop, gm, gl, ga);

    // Output projection (A and W both pre-rounded: no cvt in mainloop)
    dim3 gg1(M / 128, D_MODEL / 128, 1);
    gemm_xwT<0, 0><<<gg1, 256, SMEM_GEMM>>>(ga, rwo, out, ga, rwo, out, ga, rwo,
                                            out);
}

// round 11
// speedup vs baseline: 1.2602x; 1.0348x over previous
#include <cuda_runtime.h>
#include <cstdint>

#define D_MODEL 512
#define NH 8
#define DH 64

// Scratch (allocation-free rule: __device__ globals).
__device__ float g_q[4096 * 512];
__device__ float g_k[4096 * 512];
__device__ float g_v[4096 * 512];
__device__ float g_att[4096 * 512];
__device__ float g_wr[4 * 512 * 512];  // tf32-rounded weights (wq,wk,wv,wo)
// Split-KV partials: up to 4 chunks per q-row (chunk = 8 kb-iters).
__device__ float g_op[4 * 4096 * 512];
__device__ float g_m[4 * 8 * 4096];
__device__ float g_l[4 * 8 * 4096];

// Work-item tables, HEAVY-FIRST (sorted by chunk length descending) so the
// block scheduler drains the 8-iter blocks first and tails on 2-iter blocks.
// (qb, ch) pairs; chunk = kb-iters [8*ch, min(8*ch+7, 2qb+1)].
// 28 eight-iter items, then 4x6, 4x4, 4x2.
__constant__ unsigned char c_qb[40] = {
    3, 4, 5, 6, 7, 7, 8, 8, 9, 9, 10, 10, 11, 11, 11, 12, 12, 12,
    13, 13, 13, 14, 14, 14, 15, 15, 15, 15,
    2, 6, 10, 14, 1, 5, 9, 13, 0, 4, 8, 12};
__constant__ unsigned char c_ch[40] = {
    0, 0, 0, 0, 0, 1, 0, 1, 0, 1, 0, 1, 0, 1, 2, 0, 1, 2,
    0, 1, 2, 0, 1, 2, 0, 1, 2, 3,
    0, 1, 2, 3, 0, 1, 2, 3, 0, 1, 2, 3};

__device__ __forceinline__ float f2tf32(float x) {
    uint32_t y;
    asm("cvt.rna.tf32.f32 %0, %1;" : "=r"(y) : "f"(x));
    return __uint_as_float(y);
}

__device__ __forceinline__ void mma_tf32(float* c, uint32_t a0, uint32_t a1,
                                         uint32_t a2, uint32_t a3, uint32_t b0,
                                         uint32_t b1) {
    asm volatile(
        "mma.sync.aligned.m16n8k8.row.col.f32.tf32.tf32.f32 "
        "{%0,%1,%2,%3}, {%4,%5,%6,%7}, {%8,%9}, {%0,%1,%2,%3};"
        : "+f"(c[0]), "+f"(c[1]), "+f"(c[2]), "+f"(c[3])
        : "r"(a0), "r"(a1), "r"(a2), "r"(a3), "r"(b0), "r"(b1));
}

__device__ __forceinline__ void cp_async16(void* smem_dst, const void* gmem_src) {
    uint32_t s = (uint32_t)__cvta_generic_to_shared(smem_dst);
    asm volatile("cp.async.cg.shared.global [%0], [%1], 16;\n" ::"r"(s),
                 "l"(gmem_src));
}
#define CP_COMMIT() asm volatile("cp.async.commit_group;\n" ::: "memory")
#define CP_WAIT0() asm volatile("cp.async.wait_group 0;\n" ::: "memory")

// ---------------------------------------------------------------------------
// Round the 4 weight matrices (512x512 each) to tf32 once.
// ---------------------------------------------------------------------------
__global__ void __launch_bounds__(256) round_w(const float4* __restrict__ w0,
                                               const float4* __restrict__ w1,
                                               const float4* __restrict__ w2,
                                               const float4* __restrict__ w3,
                                               float4* __restrict__ out) {
    const int i = blockIdx.x * 256 + threadIdx.x;
    const int which = i >> 16;
    const int j = i & 65535;
    const float4 v = (which == 0) ? w0[j] : (which == 1) ? w1[j]
                     : (which == 2) ? w2[j] : w3[j];
    out[i] = make_float4(f2tf32(v.x), f2tf32(v.y), f2tf32(v.z), f2tf32(v.w));
}

// ---------------------------------------------------------------------------
// C[M,512] = A[M,512] @ W[512,512]^T  via tf32 mma, cp.async 2-stage pipeline.
// BM=128, BN=128, BK=32. 256 threads = 8 warps (2m x 4n), warp tile 64x32.
// blockIdx.z selects one of 3 (A, W, C) triples. W must be pre-rounded tf32.
// CVT_A: round A fragments at load (raw inputs); 0 when A is already tf32.
// ---------------------------------------------------------------------------
#define GSTR 36
#define SMEM_GEMM (2 * 2 * 128 * GSTR * 4)

template <int ROUND_OUT, int CVT_A>
__global__ void __launch_bounds__(256, 2)
    gemm_xwT(const float* __restrict__ A0, const float* __restrict__ W0,
             float* __restrict__ C0, const float* __restrict__ A1,
             const float* __restrict__ W1, float* __restrict__ C1,
             const float* __restrict__ A2, const float* __restrict__ W2,
             float* __restrict__ C2) {
    extern __shared__ float smg[];
    float* As = smg;                    // [2][128][GSTR]
    float* Ws = smg + 2 * 128 * GSTR;   // [2][128][GSTR]

    const int z = blockIdx.z;
    const float* A = (z == 0) ? A0 : (z == 1) ? A1 : A2;
    const float* W = (z == 0) ? W0 : (z == 1) ? W1 : W2;
    float* C = (z == 0) ? C0 : (z == 1) ? C1 : C2;

    const int tid = threadIdx.x;
    const int lane = tid & 31, wid = tid >> 5;
    const int g = lane >> 2, tg = lane & 3;
    const int warp_m = wid >> 2, warp_n = wid & 3;
    const int row0 = blockIdx.x * 128, col0 = blockIdx.y * 128;

    float acc[4][4][4];
#pragma unroll
    for (int mi = 0; mi < 4; mi++)
#pragma unroll
        for (int ni = 0; ni < 4; ni++)
#pragma unroll
            for (int c = 0; c < 4; c++) acc[mi][ni][c] = 0.f;

    auto load_stage = [&](int k0, int st) {
        float* Ad = As + st * 128 * GSTR;
        float* Wd = Ws + st * 128 * GSTR;
#pragma unroll
        for (int i = 0; i < 4; i++) {
            const int f4 = tid + i * 256;
            const int r = f4 >> 3, c = (f4 & 7) * 4;
            cp_async16(Ad + r * GSTR + c, A + (size_t)(row0 + r) * D_MODEL + k0 + c);
            cp_async16(Wd + r * GSTR + c, W + (size_t)(col0 + r) * D_MODEL + k0 + c);
        }
        CP_COMMIT();
    };

    load_stage(0, 0);

    for (int it = 0; it < 16; it++) {
        CP_WAIT0();
        __syncthreads();
        if (it + 1 < 16) load_stage((it + 1) * 32, (it + 1) & 1);

        const float* Ab = As + (it & 1) * 128 * GSTR;
        const float* Wb = Ws + (it & 1) * 128 * GSTR;
#pragma unroll
        for (int ks = 0; ks < 4; ks++) {
            const int kk = ks * 8;
            uint32_t a[4][4];
#pragma unroll
            for (int mi = 0; mi < 4; mi++) {
                const int rm = warp_m * 64 + mi * 16;
                float e0 = Ab[(rm + g) * GSTR + kk + tg];
                float e1 = Ab[(rm + 8 + g) * GSTR + kk + tg];
                float e2 = Ab[(rm + g) * GSTR + kk + tg + 4];
                float e3 = Ab[(rm + 8 + g) * GSTR + kk + tg + 4];
                if (CVT_A) {
                    e0 = f2tf32(e0); e1 = f2tf32(e1);
                    e2 = f2tf32(e2); e3 = f2tf32(e3);
                }
                a[mi][0] = __float_as_uint(e0);
                a[mi][1] = __float_as_uint(e1);
                a[mi][2] = __float_as_uint(e2);
                a[mi][3] = __float_as_uint(e3);
            }
#pragma unroll
            for (int ni = 0; ni < 4; ni++) {
                const int nb = warp_n * 32 + ni * 8;
                uint32_t b0 = __float_as_uint(Wb[(nb + g) * GSTR + kk + tg]);
                uint32_t b1 = __float_as_uint(Wb[(nb + g) * GSTR + kk + tg + 4]);
#pragma unroll
                for (int mi = 0; mi < 4; mi++)
                    mma_tf32(acc[mi][ni], a[mi][0], a[mi][1], a[mi][2], a[mi][3],
                             b0, b1);
            }
        }
    }

#pragma unroll
    for (int mi = 0; mi < 4; mi++) {
#pragma unroll
        for (int ni = 0; ni < 4; ni++) {
            const int r = row0 + warp_m * 64 + mi * 16 + g;
            const int c = col0 + warp_n * 32 + ni * 8 + 2 * tg;
            float v0 = acc[mi][ni][0], v1 = acc[mi][ni][1];
            float v2 = acc[mi][ni][2], v3 = acc[mi][ni][3];
            if (ROUND_OUT) {
                v0 = f2tf32(v0); v1 = f2tf32(v1);
                v2 = f2tf32(v2); v3 = f2tf32(v3);
            }
            *(float2*)(C + (size_t)r * D_MODEL + c) = make_float2(v0, v1);
            *(float2*)(C + (size_t)(r + 8) * D_MODEL + c) = make_float2(v2, v3);
        }
    }
}

// ---------------------------------------------------------------------------
// Split-KV flash attention, tf32 mma. Br=128, Bc=64, 256 threads (8 warps x
// 16 rows). Each block: one (bh, q-tile, 8-iteration KV chunk) -> writes
// UNNORMALIZED O partial + per-row (m, l). Inputs pre-rounded tf32.
// Block mapping is ITEM-MAJOR over a heavy-first table: bh = bid % 16,
// item = bid / 16, so the longest blocks are scheduled first (LPT).
// ---------------------------------------------------------------------------
#define QSTR 68
#define VSTR 72
#define SMEM_ATTN ((128 * QSTR + 2 * 64 * QSTR + 2 * 64 * VSTR) * 4)

__global__ void __launch_bounds__(256, 2)
    attn_kernel(const float* __restrict__ Qg, const float* __restrict__ Kg,
                const float* __restrict__ Vg, float* __restrict__ Op,
                float* __restrict__ Mp, float* __restrict__ Lp, int SEQ) {
    extern __shared__ float sm[];
    float* Qs = sm;                         // [128][QSTR]
    float* Ks = sm + 128 * QSTR;            // [2][64][QSTR]
    float* Vs = Ks + 2 * 64 * QSTR;         // [2][64][VSTR]

    const float inv_scale = 0.044194173824159216f;  // 1/sqrt(512)
    const int tid = threadIdx.x;
    const int lane = tid & 31, wid = tid >> 5;
    const int g = lane >> 2, tg = lane & 3;
    const int r0 = wid * 16;
    const int bh = blockIdx.x & 15;          // item-major: heavy items first
    const int item = blockIdx.x >> 4;
    const int qb = c_qb[item];
    const int ch = c_ch[item];
    const int b = bh >> 3, h = bh & 7;
    const size_t rowbase = (size_t)b * SEQ;
    const int colh = h * DH;
    const int kbmax = 2 * qb + 1;
    const int kb0 = ch * 8;
    const int kbe = min(kb0 + 7, kbmax);

    auto load_kv = [&](int kb, int st) {
        const float* Kb = Kg + (rowbase + kb * 64) * D_MODEL + colh;
        const float* Vb = Vg + (rowbase + kb * 64) * D_MODEL + colh;
        float* Kd = Ks + st * 64 * QSTR;
        float* Vd = Vs + st * 64 * VSTR;
#pragma unroll
        for (int i = 0; i < 4; i++) {
            const int f4 = tid + i * 256;
            const int r = f4 >> 4, c = (f4 & 15) * 4;
            cp_async16(Kd + r * QSTR + c, Kb + (size_t)r * D_MODEL + c);
            cp_async16(Vd + r * VSTR + c, Vb + (size_t)r * D_MODEL + c);
        }
        CP_COMMIT();
    };

    load_kv(kb0, kb0 & 1);

    // Q tile [128 x 64] (pre-rounded tf32)
#pragma unroll
    for (int i = 0; i < 8; i++) {
        const int f4 = tid + i * 256;
        const int r = f4 >> 4, c = (f4 & 15) * 4;
        float4 v = *(const float4*)(Qg + (rowbase + qb * 128 + r) * D_MODEL + colh + c);
        Qs[r * QSTR + c + 0] = v.x; Qs[r * QSTR + c + 1] = v.y;
        Qs[r * QSTR + c + 2] = v.z; Qs[r * QSTR + c + 3] = v.w;
    }

    float m[2] = {-1e30f, -1e30f}, l[2] = {0.f, 0.f};
    float oacc[8][4];
#pragma unroll
    for (int ni = 0; ni < 8; ni++)
#pragma unroll
        for (int c = 0; c < 4; c++) oacc[ni][c] = 0.f;

    for (int kb = kb0; kb <= kbe; kb++) {
        CP_WAIT0();
        __syncthreads();
        if (kb + 1 <= kbe) load_kv(kb + 1, (kb + 1) & 1);

        const float* Kb = Ks + (kb & 1) * 64 * QSTR;
        const float* Vb = Vs + (kb & 1) * 64 * VSTR;

        const int joff = kb * 64 - qb * 128;
        if (joff > r0 + 15) continue;           // warp fully masked
        const bool need_mask = (joff + 63 > r0);

        float sacc[8][4];
#pragma unroll
        for (int ni = 0; ni < 8; ni++)
#pragma unroll
            for (int c = 0; c < 4; c++) sacc[ni][c] = 0.f;

#pragma unroll
        for (int ks = 0; ks < 8; ks++) {
            const int kk = ks * 8;
            uint32_t a0 = __float_as_uint(Qs[(r0 + g) * QSTR + kk + tg]);
            uint32_t a1 = __float_as_uint(Qs[(r0 + 8 + g) * QSTR + kk + tg]);
            uint32_t a2 = __float_as_uint(Qs[(r0 + g) * QSTR + kk + tg + 4]);
            uint32_t a3 = __float_as_uint(Qs[(r0 + 8 + g) * QSTR + kk + tg + 4]);
#pragma unroll
            for (int ni = 0; ni < 8; ni++) {
                uint32_t b0 = __float_as_uint(Kb[(ni * 8 + g) * QSTR + kk + tg]);
                uint32_t b1 = __float_as_uint(Kb[(ni * 8 + g) * QSTR + kk + tg + 4]);
                mma_tf32(sacc[ni], a0, a1, a2, a3, b0, b1);
            }
        }

        // scale + causal mask ((x-1e10)/scale underflows expf to 0 == -1e30)
#pragma unroll
        for (int ni = 0; ni < 8; ni++)
#pragma unroll
            for (int c = 0; c < 4; c++) {
                float sv = sacc[ni][c] * inv_scale;
                if (need_mask) {
                    const int j = joff + ni * 8 + 2 * tg + (c & 1);
                    const int r = r0 + g + (c >> 1) * 8;
                    if (j > r) sv = -1e30f;
                }
                sacc[ni][c] = sv;
            }

        // online softmax per row-half
#pragma unroll
        for (int i = 0; i < 2; i++) {
            float rmax = -1e30f;
#pragma unroll
            for (int ni = 0; ni < 8; ni++)
                rmax = fmaxf(rmax, fmaxf(sacc[ni][i * 2], sacc[ni][i * 2 + 1]));
            rmax = fmaxf(rmax, __shfl_xor_sync(0xffffffffu, rmax, 1));
            rmax = fmaxf(rmax, __shfl_xor_sync(0xffffffffu, rmax, 2));
            const float mnew = fmaxf(m[i], rmax);
            const float corr = __expf(m[i] - mnew);
            float rsum = 0.f;
#pragma unroll
            for (int ni = 0; ni < 8; ni++) {
                float p0 = __expf(sacc[ni][i * 2] - mnew);
                float p1 = __expf(sacc[ni][i * 2 + 1] - mnew);
                sacc[ni][i * 2] = p0;
                sacc[ni][i * 2 + 1] = p1;
                rsum += p0 + p1;
            }
            rsum += __shfl_xor_sync(0xffffffffu, rsum, 1);
            rsum += __shfl_xor_sync(0xffffffffu, rsum, 2);
            l[i] = l[i] * corr + rsum;
            m[i] = mnew;
#pragma unroll
            for (int ni = 0; ni < 8; ni++) {
                oacc[ni][i * 2] *= corr;
                oacc[ni][i * 2 + 1] *= corr;
            }
        }

        // O += P V : C-fragment -> A-fragment via intra-quad shuffles
        const int src0 = (lane & ~3) | (tg >> 1);
        const bool odd = tg & 1;
#pragma unroll
        for (int ks = 0; ks < 8; ks++) {
            float p00 = __shfl_sync(0xffffffffu, sacc[ks][0], src0);
            float p01 = __shfl_sync(0xffffffffu, sacc[ks][1], src0);
            float p10 = __shfl_sync(0xffffffffu, sacc[ks][2], src0);
            float p11 = __shfl_sync(0xffffffffu, sacc[ks][3], src0);
            float q00 = __shfl_sync(0xffffffffu, sacc[ks][0], src0 + 2);
            float q01 = __shfl_sync(0xffffffffu, sacc[ks][1], src0 + 2);
            float q10 = __shfl_sync(0xffffffffu, sacc[ks][2], src0 + 2);
            float q11 = __shfl_sync(0xffffffffu, sacc[ks][3], src0 + 2);
            uint32_t a0 = __float_as_uint(f2tf32(odd ? p01 : p00));
            uint32_t a1 = __float_as_uint(f2tf32(odd ? p11 : p10));
            uint32_t a2 = __float_as_uint(f2tf32(odd ? q01 : q00));
            uint32_t a3 = __float_as_uint(f2tf32(odd ? q11 : q10));
            const int j0 = ks * 8;
#pragma unroll
            for (int ni = 0; ni < 8; ni++) {
                uint32_t b0 = __float_as_uint(Vb[(j0 + tg) * VSTR + ni * 8 + g]);
                uint32_t b1 = __float_as_uint(Vb[(j0 + tg + 4) * VSTR + ni * 8 + g]);
                mma_tf32(oacc[ni], a0, a1, a2, a3, b0, b1);
            }
        }
    }

    // Write UNNORMALIZED partials + (m, l)
    float* op = Op + (size_t)ch * 4096 * 512;
    const size_t rA = rowbase + qb * 128 + r0 + g;
#pragma unroll
    for (int ni = 0; ni < 8; ni++) {
        const int c = colh + ni * 8 + 2 * tg;
        *(float2*)(op + rA * D_MODEL + c) = make_float2(oacc[ni][0], oacc[ni][1]);
        *(float2*)(op + (rA + 8) * D_MODEL + c) = make_float2(oacc[ni][2], oacc[ni][3]);
    }
    if (tg == 0) {
        const size_t mlb = (size_t)(ch * 8 + h) * 4096;
        Mp[mlb + rA] = m[0];
        Lp[mlb + rA] = l[0];
        Mp[mlb + rA + 8] = m[1];
        Lp[mlb + rA + 8] = l[1];
    }
}

// ---------------------------------------------------------------------------
// Combine split-KV partials: exact softmax merge, normalize, round to tf32
// (so the wo-GEMM needs no cvt; identical value to cvt-at-fragment-load).
// ---------------------------------------------------------------------------
__global__ void __launch_bounds__(256) combine_kernel(
    const float* __restrict__ Op, const float* __restrict__ Mp,
    const float* __restrict__ Lp, float* __restrict__ Og) {
    const int tid = threadIdx.x;
    const int u = blockIdx.x * 8 + (tid >> 5);  // (row, head) unit
    const int row = u >> 3, h = u & 7;
    const int j = (tid & 31) * 2;
    const int qb = (row >> 7) & 15;
    const int nch = (qb >> 2) + 1;

    float mv[4], lv[4];
    float mg = -1e30f;
#pragma unroll
    for (int c = 0; c < 4; c++)
        if (c < nch) {
            mv[c] = Mp[(size_t)(c * 8 + h) * 4096 + row];
            lv[c] = Lp[(size_t)(c * 8 + h) * 4096 + row];
            mg = fmaxf(mg, mv[c]);
        }
    float lg = 0.f;
    float2 o = make_float2(0.f, 0.f);
#pragma unroll
    for (int c = 0; c < 4; c++)
        if (c < nch) {
            const float sc = __expf(mv[c] - mg);
            lg += sc * lv[c];
            float2 p = *(const float2*)(Op + (size_t)c * 4096 * 512 +
                                        (size_t)row * 512 + h * 64 + j);
            o.x += sc * p.x;
            o.y += sc * p.y;
        }
    const float inv = 1.f / lg;
    *(float2*)(Og + (size_t)row * 512 + h * 64 + j) =
        make_float2(f2tf32(o.x * inv), f2tf32(o.y * inv));
}

// ---------------------------------------------------------------------------
extern "C" void kernel_launch(void* const* d_in, const int* in_sizes, int n_in,
                              void* d_out, int out_size) {
    const float* q  = (const float*)d_in[0];
    const float* k  = (const float*)d_in[1];
    const float* v  = (const float*)d_in[2];
    const float* wq = (const float*)d_in[3];
    const float* wk = (const float*)d_in[4];
    const float* wv = (const float*)d_in[5];
    const float* wo = (const float*)d_in[6];
    float* out = (float*)d_out;

    const int M = in_sizes[0] / D_MODEL;  // B*S = 4096
    const int B = 2;
    const int SEQ = M / B;                // 2048

    float *gq, *gk, *gv, *ga, *gwr, *gop, *gm, *gl;
    cudaGetSymbolAddress((void**)&gq, g_q);
    cudaGetSymbolAddress((void**)&gk, g_k);
    cudaGetSymbolAddress((void**)&gv, g_v);
    cudaGetSymbolAddress((void**)&ga, g_att);
    cudaGetSymbolAddress((void**)&gwr, g_wr);
    cudaGetSymbolAddress((void**)&gop, g_op);
    cudaGetSymbolAddress((void**)&gm, g_m);
    cudaGetSymbolAddress((void**)&gl, g_l);

    cudaFuncSetAttribute(gemm_xwT<1, 1>,
                         cudaFuncAttributeMaxDynamicSharedMemorySize, SMEM_GEMM);
    cudaFuncSetAttribute(gemm_xwT<0, 0>,
                         cudaFuncAttributeMaxDynamicSharedMemorySize, SMEM_GEMM);
    cudaFuncSetAttribute(attn_kernel, cudaFuncAttributeMaxDynamicSharedMemorySize,
                         SMEM_ATTN);

    // Round all 4 weight matrices to tf32 once.
    round_w<<<1024, 256>>>((const float4*)wq, (const float4*)wk,
                           (const float4*)wv, (const float4*)wo, (float4*)gwr);
    const float* rwq = gwr;
    const float* rwk = gwr + 512 * 512;
    const float* rwv = gwr + 2 * 512 * 512;
    const float* rwo = gwr + 3 * 512 * 512;

    // Fused projection: q/k/v GEMMs in one launch (blockIdx.z selects).
    dim3 gg3(M / 128, D_MODEL / 128, 3);
    gemm_xwT<1, 1><<<gg3, 256, SMEM_GEMM>>>(q, rwq, gq, k, rwk, gk, v, rwv, gv);

    // Split-KV attention: 40 heavy-first items x 16 bh (item-major mapping).
    attn_kernel<<<16 * 40, 256, SMEM_ATTN>>>(gq, gk, gv, gop, gm, gl, SEQ);

    // Combine partials -> g_att (tf32-rounded)
    combine_kernel<<<4096 * 8 / 8, 256>>>(gop, gm, gl, ga);

    // Output projection (A and W both pre-rounded: no cvt in mainloop)
    dim3 gg1(M / 128, D_MODEL / 128, 1);
    gemm_xwT<0, 0><<<gg1, 256, SMEM_GEMM>>>(ga, rwo, out, ga, rwo, out, ga, rwo,
                                            out);
}

// round 12
// speedup vs baseline: 1.3428x; 1.0655x over previous
#include <cuda_runtime.h>
#include <cstdint>

#define D_MODEL 512
#define NH 8
#define DH 64

// Scratch (allocation-free rule: __device__ globals).
__device__ float g_q[4096 * 512];
__device__ float g_k[4096 * 512];
__device__ float g_v[4096 * 512];
__device__ float g_att[4096 * 512];
__device__ float g_wr[4 * 512 * 512];  // tf32-rounded weights (wq,wk,wv,wo)
// Split-KV partials: up to 4 chunks per q-row (chunk = 8 kb-iters).
__device__ float g_op[4 * 4096 * 512];
__device__ float g_m[4 * 8 * 4096];
__device__ float g_l[4 * 8 * 4096];

// Work-item tables, HEAVY-FIRST (LPT). (qb, ch); chunk = [8ch, min(8ch+7, 2qb+1)].
__constant__ unsigned char c_qb[40] = {
    3, 4, 5, 6, 7, 7, 8, 8, 9, 9, 10, 10, 11, 11, 11, 12, 12, 12,
    13, 13, 13, 14, 14, 14, 15, 15, 15, 15,
    2, 6, 10, 14, 1, 5, 9, 13, 0, 4, 8, 12};
__constant__ unsigned char c_ch[40] = {
    0, 0, 0, 0, 0, 1, 0, 1, 0, 1, 0, 1, 0, 1, 2, 0, 1, 2,
    0, 1, 2, 0, 1, 2, 0, 1, 2, 3,
    0, 1, 2, 3, 0, 1, 2, 3, 0, 1, 2, 3};

__device__ __forceinline__ float f2tf32(float x) {
    uint32_t y;
    asm("cvt.rna.tf32.f32 %0, %1;" : "=r"(y) : "f"(x));
    return __uint_as_float(y);
}

__device__ __forceinline__ void mma_tf32(float* c, uint32_t a0, uint32_t a1,
                                         uint32_t a2, uint32_t a3, uint32_t b0,
                                         uint32_t b1) {
    asm volatile(
        "mma.sync.aligned.m16n8k8.row.col.f32.tf32.tf32.f32 "
        "{%0,%1,%2,%3}, {%4,%5,%6,%7}, {%8,%9}, {%0,%1,%2,%3};"
        : "+f"(c[0]), "+f"(c[1]), "+f"(c[2]), "+f"(c[3])
        : "r"(a0), "r"(a1), "r"(a2), "r"(a3), "r"(b0), "r"(b1));
}

__device__ __forceinline__ void cp_async16(void* smem_dst, const void* gmem_src) {
    uint32_t s = (uint32_t)__cvta_generic_to_shared(smem_dst);
    asm volatile("cp.async.cg.shared.global [%0], [%1], 16;\n" ::"r"(s),
                 "l"(gmem_src));
}
#define CP_COMMIT() asm volatile("cp.async.commit_group;\n" ::: "memory")
#define CP_WAIT0() asm volatile("cp.async.wait_group 0;\n" ::: "memory")

// ---------------------------------------------------------------------------
// Round the 4 weight matrices (512x512 each) to tf32 once.
// ---------------------------------------------------------------------------
__global__ void __launch_bounds__(256) round_w(const float4* __restrict__ w0,
                                               const float4* __restrict__ w1,
                                               const float4* __restrict__ w2,
                                               const float4* __restrict__ w3,
                                               float4* __restrict__ out) {
    const int i = blockIdx.x * 256 + threadIdx.x;
    const int which = i >> 16;
    const int j = i & 65535;
    const float4 v = (which == 0) ? w0[j] : (which == 1) ? w1[j]
                     : (which == 2) ? w2[j] : w3[j];
    out[i] = make_float4(f2tf32(v.x), f2tf32(v.y), f2tf32(v.z), f2tf32(v.w));
}

// ---------------------------------------------------------------------------
// C[M,512] = A[M,512] @ W[512,512]^T  via tf32 mma, cp.async 2-stage pipeline.
// BM=128, BN=128, BK=32. 256 threads = 8 warps (2m x 4n), warp tile 64x32.
// blockIdx.z selects one of 3 (A, W, C) triples. W must be pre-rounded tf32.
// CVT_A: round A fragments at load (raw inputs); 0 when A is already tf32.
// ---------------------------------------------------------------------------
#define GSTR 36
#define SMEM_GEMM (2 * 2 * 128 * GSTR * 4)

template <int ROUND_OUT, int CVT_A>
__global__ void __launch_bounds__(256, 2)
    gemm_xwT(const float* __restrict__ A0, const float* __restrict__ W0,
             float* __restrict__ C0, const float* __restrict__ A1,
             const float* __restrict__ W1, float* __restrict__ C1,
             const float* __restrict__ A2, const float* __restrict__ W2,
             float* __restrict__ C2) {
    extern __shared__ float smg[];
    float* As = smg;                    // [2][128][GSTR]
    float* Ws = smg + 2 * 128 * GSTR;   // [2][128][GSTR]

    const int z = blockIdx.z;
    const float* A = (z == 0) ? A0 : (z == 1) ? A1 : A2;
    const float* W = (z == 0) ? W0 : (z == 1) ? W1 : W2;
    float* C = (z == 0) ? C0 : (z == 1) ? C1 : C2;

    const int tid = threadIdx.x;
    const int lane = tid & 31, wid = tid >> 5;
    const int g = lane >> 2, tg = lane & 3;
    const int warp_m = wid >> 2, warp_n = wid & 3;
    const int row0 = blockIdx.x * 128, col0 = blockIdx.y * 128;

    float acc[4][4][4];
#pragma unroll
    for (int mi = 0; mi < 4; mi++)
#pragma unroll
        for (int ni = 0; ni < 4; ni++)
#pragma unroll
            for (int c = 0; c < 4; c++) acc[mi][ni][c] = 0.f;

    auto load_stage = [&](int k0, int st) {
        float* Ad = As + st * 128 * GSTR;
        float* Wd = Ws + st * 128 * GSTR;
#pragma unroll
        for (int i = 0; i < 4; i++) {
            const int f4 = tid + i * 256;
            const int r = f4 >> 3, c = (f4 & 7) * 4;
            cp_async16(Ad + r * GSTR + c, A + (size_t)(row0 + r) * D_MODEL + k0 + c);
            cp_async16(Wd + r * GSTR + c, W + (size_t)(col0 + r) * D_MODEL + k0 + c);
        }
        CP_COMMIT();
    };

    load_stage(0, 0);

    for (int it = 0; it < 16; it++) {
        CP_WAIT0();
        __syncthreads();
        if (it + 1 < 16) load_stage((it + 1) * 32, (it + 1) & 1);

        const float* Ab = As + (it & 1) * 128 * GSTR;
        const float* Wb = Ws + (it & 1) * 128 * GSTR;
#pragma unroll
        for (int ks = 0; ks < 4; ks++) {
            const int kk = ks * 8;
            uint32_t a[4][4];
#pragma unroll
            for (int mi = 0; mi < 4; mi++) {
                const int rm = warp_m * 64 + mi * 16;
                float e0 = Ab[(rm + g) * GSTR + kk + tg];
                float e1 = Ab[(rm + 8 + g) * GSTR + kk + tg];
                float e2 = Ab[(rm + g) * GSTR + kk + tg + 4];
                float e3 = Ab[(rm + 8 + g) * GSTR + kk + tg + 4];
                if (CVT_A) {
                    e0 = f2tf32(e0); e1 = f2tf32(e1);
                    e2 = f2tf32(e2); e3 = f2tf32(e3);
                }
                a[mi][0] = __float_as_uint(e0);
                a[mi][1] = __float_as_uint(e1);
                a[mi][2] = __float_as_uint(e2);
                a[mi][3] = __float_as_uint(e3);
            }
#pragma unroll
            for (int ni = 0; ni < 4; ni++) {
                const int nb = warp_n * 32 + ni * 8;
                uint32_t b0 = __float_as_uint(Wb[(nb + g) * GSTR + kk + tg]);
                uint32_t b1 = __float_as_uint(Wb[(nb + g) * GSTR + kk + tg + 4]);
#pragma unroll
                for (int mi = 0; mi < 4; mi++)
                    mma_tf32(acc[mi][ni], a[mi][0], a[mi][1], a[mi][2], a[mi][3],
                             b0, b1);
            }
        }
    }

#pragma unroll
    for (int mi = 0; mi < 4; mi++) {
#pragma unroll
        for (int ni = 0; ni < 4; ni++) {
            const int r = row0 + warp_m * 64 + mi * 16 + g;
            const int c = col0 + warp_n * 32 + ni * 8 + 2 * tg;
            float v0 = acc[mi][ni][0], v1 = acc[mi][ni][1];
            float v2 = acc[mi][ni][2], v3 = acc[mi][ni][3];
            if (ROUND_OUT) {
                v0 = f2tf32(v0); v1 = f2tf32(v1);
                v2 = f2tf32(v2); v3 = f2tf32(v3);
            }
            *(float2*)(C + (size_t)r * D_MODEL + c) = make_float2(v0, v1);
            *(float2*)(C + (size_t)(r + 8) * D_MODEL + c) = make_float2(v2, v3);
        }
    }
}

// ---------------------------------------------------------------------------
// Split-KV flash attention, tf32 mma. Br=128, Bc=64, 128 threads = 4 warps,
// each warp owns 32 q-rows (two 16-row mma tiles) so shared K/V fragment
// reads are amortized 2x (smem crossbar was the limiter at 8 warps).
// Block = (bh, q-tile, 8-iter KV chunk) -> UNNORMALIZED O partial + (m,l).
// Item-major heavy-first mapping (LPT): bh = bid % 16, item = bid / 16.
// ---------------------------------------------------------------------------
#define QSTR 68
#define VSTR 72
#define SMEM_ATTN ((128 * QSTR + 2 * 64 * QSTR + 2 * 64 * VSTR) * 4)

__global__ void __launch_bounds__(128, 2)
    attn_kernel(const float* __restrict__ Qg, const float* __restrict__ Kg,
                const float* __restrict__ Vg, float* __restrict__ Op,
                float* __restrict__ Mp, float* __restrict__ Lp, int SEQ) {
    extern __shared__ float sm[];
    float* Qs = sm;                         // [128][QSTR]
    float* Ks = sm + 128 * QSTR;            // [2][64][QSTR]
    float* Vs = Ks + 2 * 64 * QSTR;         // [2][64][VSTR]

    const float inv_scale = 0.044194173824159216f;  // 1/sqrt(512)
    const int tid = threadIdx.x;
    const int lane = tid & 31, wid = tid >> 5;
    const int g = lane >> 2, tg = lane & 3;
    const int r0 = wid * 32;                 // warp's 32 q-rows
    const int bh = blockIdx.x & 15;
    const int item = blockIdx.x >> 4;
    const int qb = c_qb[item];
    const int ch = c_ch[item];
    const int b = bh >> 3, h = bh & 7;
    const size_t rowbase = (size_t)b * SEQ;
    const int colh = h * DH;
    const int kbmax = 2 * qb + 1;
    const int kb0 = ch * 8;
    const int kbe = min(kb0 + 7, kbmax);

    auto load_kv = [&](int kb, int st) {
        const float* Kb = Kg + (rowbase + kb * 64) * D_MODEL + colh;
        const float* Vb = Vg + (rowbase + kb * 64) * D_MODEL + colh;
        float* Kd = Ks + st * 64 * QSTR;
        float* Vd = Vs + st * 64 * VSTR;
#pragma unroll
        for (int i = 0; i < 8; i++) {
            const int f4 = tid + i * 128;
            const int r = f4 >> 4, c = (f4 & 15) * 4;
            cp_async16(Kd + r * QSTR + c, Kb + (size_t)r * D_MODEL + c);
            cp_async16(Vd + r * VSTR + c, Vb + (size_t)r * D_MODEL + c);
        }
        CP_COMMIT();
    };

    load_kv(kb0, kb0 & 1);

    // Q tile [128 x 64] (pre-rounded tf32)
#pragma unroll
    for (int i = 0; i < 16; i++) {
        const int f4 = tid + i * 128;
        const int r = f4 >> 4, c = (f4 & 15) * 4;
        float4 v = *(const float4*)(Qg + (rowbase + qb * 128 + r) * D_MODEL + colh + c);
        Qs[r * QSTR + c + 0] = v.x; Qs[r * QSTR + c + 1] = v.y;
        Qs[r * QSTR + c + 2] = v.z; Qs[r * QSTR + c + 3] = v.w;
    }

    // row-group rg (0..3): row = r0 + rg*8 + g. rt = rg>>1 (16-row mma tile).
    float m[4] = {-1e30f, -1e30f, -1e30f, -1e30f};
    float l[4] = {0.f, 0.f, 0.f, 0.f};
    float oacc[8][2][4];
#pragma unroll
    for (int ni = 0; ni < 8; ni++)
#pragma unroll
        for (int rt = 0; rt < 2; rt++)
#pragma unroll
            for (int c = 0; c < 4; c++) oacc[ni][rt][c] = 0.f;

    for (int kb = kb0; kb <= kbe; kb++) {
        CP_WAIT0();
        __syncthreads();
        if (kb + 1 <= kbe) load_kv(kb + 1, (kb + 1) & 1);

        const float* Kb = Ks + (kb & 1) * 64 * QSTR;
        const float* Vb = Vs + (kb & 1) * 64 * VSTR;

        const int joff = kb * 64 - qb * 128;
        if (joff > r0 + 31) continue;           // warp fully masked
        const bool need_mask = (joff + 63 > r0);

        float sacc[8][2][4];
#pragma unroll
        for (int ni = 0; ni < 8; ni++)
#pragma unroll
            for (int rt = 0; rt < 2; rt++)
#pragma unroll
                for (int c = 0; c < 4; c++) sacc[ni][rt][c] = 0.f;

        // S = Q K^T : K fragments shared across both 16-row tiles.
#pragma unroll
        for (int ks = 0; ks < 8; ks++) {
            const int kk = ks * 8;
            uint32_t a[2][4];
#pragma unroll
            for (int rt = 0; rt < 2; rt++) {
                const int rr = r0 + rt * 16;
                a[rt][0] = __float_as_uint(Qs[(rr + g) * QSTR + kk + tg]);
                a[rt][1] = __float_as_uint(Qs[(rr + 8 + g) * QSTR + kk + tg]);
                a[rt][2] = __float_as_uint(Qs[(rr + g) * QSTR + kk + tg + 4]);
                a[rt][3] = __float_as_uint(Qs[(rr + 8 + g) * QSTR + kk + tg + 4]);
            }
#pragma unroll
            for (int ni = 0; ni < 8; ni++) {
                uint32_t b0 = __float_as_uint(Kb[(ni * 8 + g) * QSTR + kk + tg]);
                uint32_t b1 = __float_as_uint(Kb[(ni * 8 + g) * QSTR + kk + tg + 4]);
                mma_tf32(sacc[ni][0], a[0][0], a[0][1], a[0][2], a[0][3], b0, b1);
                mma_tf32(sacc[ni][1], a[1][0], a[1][1], a[1][2], a[1][3], b0, b1);
            }
        }

        // scale + causal mask ((x-1e10)/scale underflows expf to 0 == -1e30)
#pragma unroll
        for (int ni = 0; ni < 8; ni++)
#pragma unroll
            for (int rt = 0; rt < 2; rt++)
#pragma unroll
                for (int c = 0; c < 4; c++) {
                    float sv = sacc[ni][rt][c] * inv_scale;
                    if (need_mask) {
                        const int j = joff + ni * 8 + 2 * tg + (c & 1);
                        const int r = r0 + rt * 16 + (c >> 1) * 8 + g;
                        if (j > r) sv = -1e30f;
                    }
                    sacc[ni][rt][c] = sv;
                }

        // online softmax per row-group rg = rt*2 + (c>>1)
#pragma unroll
        for (int rg = 0; rg < 4; rg++) {
            const int rt = rg >> 1, ci = (rg & 1) * 2;
            float rmax = -1e30f;
#pragma unroll
            for (int ni = 0; ni < 8; ni++)
                rmax = fmaxf(rmax, fmaxf(sacc[ni][rt][ci], sacc[ni][rt][ci + 1]));
            rmax = fmaxf(rmax, __shfl_xor_sync(0xffffffffu, rmax, 1));
            rmax = fmaxf(rmax, __shfl_xor_sync(0xffffffffu, rmax, 2));
            const float mnew = fmaxf(m[rg], rmax);
            const float corr = __expf(m[rg] - mnew);
            float rsum = 0.f;
#pragma unroll
            for (int ni = 0; ni < 8; ni++) {
                float p0 = __expf(sacc[ni][rt][ci] - mnew);
                float p1 = __expf(sacc[ni][rt][ci + 1] - mnew);
                sacc[ni][rt][ci] = p0;
                sacc[ni][rt][ci + 1] = p1;
                rsum += p0 + p1;
            }
            rsum += __shfl_xor_sync(0xffffffffu, rsum, 1);
            rsum += __shfl_xor_sync(0xffffffffu, rsum, 2);
            l[rg] = l[rg] * corr + rsum;
            m[rg] = mnew;
#pragma unroll
            for (int ni = 0; ni < 8; ni++) {
                oacc[ni][rt][ci] *= corr;
                oacc[ni][rt][ci + 1] *= corr;
            }
        }

        // O += P V : P C-frag -> A-frag via intra-quad shuffles (per rt);
        // V fragments shared across both row tiles.
        const int src0 = (lane & ~3) | (tg >> 1);
        const bool odd = tg & 1;
#pragma unroll
        for (int ks = 0; ks < 8; ks++) {
            uint32_t aA[2][4];
#pragma unroll
            for (int rt = 0; rt < 2; rt++) {
                float p00 = __shfl_sync(0xffffffffu, sacc[ks][rt][0], src0);
                float p01 = __shfl_sync(0xffffffffu, sacc[ks][rt][1], src0);
                float p10 = __shfl_sync(0xffffffffu, sacc[ks][rt][2], src0);
                float p11 = __shfl_sync(0xffffffffu, sacc[ks][rt][3], src0);
                float q00 = __shfl_sync(0xffffffffu, sacc[ks][rt][0], src0 + 2);
                float q01 = __shfl_sync(0xffffffffu, sacc[ks][rt][1], src0 + 2);
                float q10 = __shfl_sync(0xffffffffu, sacc[ks][rt][2], src0 + 2);
                float q11 = __shfl_sync(0xffffffffu, sacc[ks][rt][3], src0 + 2);
                aA[rt][0] = __float_as_uint(f2tf32(odd ? p01 : p00));
                aA[rt][1] = __float_as_uint(f2tf32(odd ? p11 : p10));
                aA[rt][2] = __float_as_uint(f2tf32(odd ? q01 : q00));
                aA[rt][3] = __float_as_uint(f2tf32(odd ? q11 : q10));
            }
            const int j0 = ks * 8;
#pragma unroll
            for (int ni = 0; ni < 8; ni++) {
                uint32_t b0 = __float_as_uint(Vb[(j0 + tg) * VSTR + ni * 8 + g]);
                uint32_t b1 = __float_as_uint(Vb[(j0 + tg + 4) * VSTR + ni * 8 + g]);
                mma_tf32(oacc[ni][0], aA[0][0], aA[0][1], aA[0][2], aA[0][3], b0, b1);
                mma_tf32(oacc[ni][1], aA[1][0], aA[1][1], aA[1][2], aA[1][3], b0, b1);
            }
        }
    }

    // Write UNNORMALIZED partials + (m, l)
    float* op = Op + (size_t)ch * 4096 * 512;
#pragma unroll
    for (int rt = 0; rt < 2; rt++) {
        const size_t rA = rowbase + qb * 128 + r0 + rt * 16 + g;
#pragma unroll
        for (int ni = 0; ni < 8; ni++) {
            const int c = colh + ni * 8 + 2 * tg;
            *(float2*)(op + rA * D_MODEL + c) =
                make_float2(oacc[ni][rt][0], oacc[ni][rt][1]);
            *(float2*)(op + (rA + 8) * D_MODEL + c) =
                make_float2(oacc[ni][rt][2], oacc[ni][rt][3]);
        }
        if (tg == 0) {
            const size_t mlb = (size_t)(ch * 8 + h) * 4096;
            Mp[mlb + rA] = m[rt * 2];
            Lp[mlb + rA] = l[rt * 2];
            Mp[mlb + rA + 8] = m[rt * 2 + 1];
            Lp[mlb + rA + 8] = l[rt * 2 + 1];
        }
    }
}

// ---------------------------------------------------------------------------
// Combine split-KV partials: exact softmax merge, normalize, round to tf32.
// ---------------------------------------------------------------------------
__global__ void __launch_bounds__(256) combine_kernel(
    const float* __restrict__ Op, const float* __restrict__ Mp,
    const float* __restrict__ Lp, float* __restrict__ Og) {
    const int tid = threadIdx.x;
    const int u = blockIdx.x * 8 + (tid >> 5);  // (row, head) unit
    const int row = u >> 3, h = u & 7;
    const int j = (tid & 31) * 2;
    const int qb = (row >> 7) & 15;
    const int nch = (qb >> 2) + 1;

    float mv[4], lv[4];
    float mg = -1e30f;
#pragma unroll
    for (int c = 0; c < 4; c++)
        if (c < nch) {
            mv[c] = Mp[(size_t)(c * 8 + h) * 4096 + row];
            lv[c] = Lp[(size_t)(c * 8 + h) * 4096 + row];
            mg = fmaxf(mg, mv[c]);
        }
    float lg = 0.f;
    float2 o = make_float2(0.f, 0.f);
#pragma unroll
    for (int c = 0; c < 4; c++)
        if (c < nch) {
            const float sc = __expf(mv[c] - mg);
            lg += sc * lv[c];
            float2 p = *(const float2*)(Op + (size_t)c * 4096 * 512 +
                                        (size_t)row * 512 + h * 64 + j);
            o.x += sc * p.x;
            o.y += sc * p.y;
        }
    const float inv = 1.f / lg;
    *(float2*)(Og + (size_t)row * 512 + h * 64 + j) =
        make_float2(f2tf32(o.x * inv), f2tf32(o.y * inv));
}

// ---------------------------------------------------------------------------
extern "C" void kernel_launch(void* const* d_in, const int* in_sizes, int n_in,
                              void* d_out, int out_size) {
    const float* q  = (const float*)d_in[0];
    const float* k  = (const float*)d_in[1];
    const float* v  = (const float*)d_in[2];
    const float* wq = (const float*)d_in[3];
    const float* wk = (const float*)d_in[4];
    const float* wv = (const float*)d_in[5];
    const float* wo = (const float*)d_in[6];
    float* out = (float*)d_out;

    const int M = in_sizes[0] / D_MODEL;  // B*S = 4096
    const int B = 2;
    const int SEQ = M / B;                // 2048

    float *gq, *gk, *gv, *ga, *gwr, *gop, *gm, *gl;
    cudaGetSymbolAddress((void**)&gq, g_q);
    cudaGetSymbolAddress((void**)&gk, g_k);
    cudaGetSymbolAddress((void**)&gv, g_v);
    cudaGetSymbolAddress((void**)&ga, g_att);
    cudaGetSymbolAddress((void**)&gwr, g_wr);
    cudaGetSymbolAddress((void**)&gop, g_op);
    cudaGetSymbolAddress((void**)&gm, g_m);
    cudaGetSymbolAddress((void**)&gl, g_l);

    cudaFuncSetAttribute(gemm_xwT<1, 1>,
                         cudaFuncAttributeMaxDynamicSharedMemorySize, SMEM_GEMM);
    cudaFuncSetAttribute(gemm_xwT<0, 0>,
                         cudaFuncAttributeMaxDynamicSharedMemorySize, SMEM_GEMM);
    cudaFuncSetAttribute(attn_kernel, cudaFuncAttributeMaxDynamicSharedMemorySize,
                         SMEM_ATTN);

    // Round all 4 weight matrices to tf32 once.
    round_w<<<1024, 256>>>((const float4*)wq, (const float4*)wk,
                           (const float4*)wv, (const float4*)wo, (float4*)gwr);
    const float* rwq = gwr;
    const float* rwk = gwr + 512 * 512;
    const float* rwv = gwr + 2 * 512 * 512;
    const float* rwo = gwr + 3 * 512 * 512;

    // Fused projection: q/k/v GEMMs in one launch (blockIdx.z selects).
    dim3 gg3(M / 128, D_MODEL / 128, 3);
    gemm_xwT<1, 1><<<gg3, 256, SMEM_GEMM>>>(q, rwq, gq, k, rwk, gk, v, rwv, gv);

    // Split-KV attention: 40 heavy-first items x 16 bh (item-major), 128 thr.
    attn_kernel<<<16 * 40, 128, SMEM_ATTN>>>(gq, gk, gv, gop, gm, gl, SEQ);

    // Combine partials -> g_att (tf32-rounded)
    combine_kernel<<<4096 * 8 / 8, 256>>>(gop, gm, gl, ga);

    // Output projection (A and W both pre-rounded: no cvt in mainloop)
    dim3 gg1(M / 128, D_MODEL / 128, 1);
    gemm_xwT<0, 0><<<gg1, 256, SMEM_GEMM>>>(ga, rwo, out, ga, rwo, out, ga, rwo,
                                            out);
}